// round 1
// baseline (speedup 1.0000x reference)
#include <cuda_runtime.h>
#include <math.h>
#include <stdint.h>

#define H   32
#define SEQ 2048
#define DH  128
#define NOUT 16
#define QMAXF 7.0f

#define BM 64
#define BN 64
#define QSTR 132   // padded row stride (floats) for 64x128 tiles, 16B aligned
#define PSTR 68    // padded row stride for 64x64 score tile

// Scratch for reconstructed (quantized + outlier) K and V. 32 MB each.
__device__ float g_kfull[(size_t)H * SEQ * DH];
__device__ float g_vfull[(size_t)H * SEQ * DH];

// ---------------------------------------------------------------------------
// K quantization: one block per (h, d) slice; outliers along the token axis.
// ---------------------------------------------------------------------------
__global__ __launch_bounds__(256) void kquant_kernel(const float* __restrict__ kin) {
    const int slice = blockIdx.x;
    const int h = slice >> 7;       // DH = 128
    const int d = slice & 127;
    const int tid = threadIdx.x;

    __shared__ float sval[SEQ];
    __shared__ float sabs[SEQ];
    __shared__ unsigned char sflag[SEQ];
    __shared__ float rv[256];
    __shared__ int   ri[256];

    const float* base = kin + (size_t)h * SEQ * DH + d;
    for (int i = tid; i < SEQ; i += 256) {
        float v = base[(size_t)i * DH];
        sval[i] = v;
        sabs[i] = fabsf(v);
        sflag[i] = 0;
    }
    __syncthreads();

    // 16 argmax passes (top_k tiebreak: larger value, then lower index)
    for (int it = 0; it < NOUT; ++it) {
        float bm = -1.0f; int bi = 0x7fffffff;
        for (int i = tid; i < SEQ; i += 256) {
            float a = sabs[i];
            if (a > bm || (a == bm && i < bi)) { bm = a; bi = i; }
        }
        rv[tid] = bm; ri[tid] = bi;
        __syncthreads();
        for (int sft = 128; sft > 0; sft >>= 1) {
            if (tid < sft) {
                float a = rv[tid + sft]; int b = ri[tid + sft];
                if (a > rv[tid] || (a == rv[tid] && b < ri[tid])) { rv[tid] = a; ri[tid] = b; }
            }
            __syncthreads();
        }
        if (tid == 0) { int w = ri[0]; sflag[w] = 1; sabs[w] = -1.0f; }
        __syncthreads();
    }

    // max |x| over remaining (dense) entries
    {
        float bm = 0.0f;
        for (int i = tid; i < SEQ; i += 256) bm = fmaxf(bm, sabs[i]);
        rv[tid] = bm;
        __syncthreads();
        for (int sft = 128; sft > 0; sft >>= 1) {
            if (tid < sft) rv[tid] = fmaxf(rv[tid], rv[tid + sft]);
            __syncthreads();
        }
    }
    const float scale = fmaxf(rv[0], 1e-6f) / QMAXF;

    for (int i = tid; i < SEQ; i += 256) {
        float v = sval[i];
        float o;
        if (sflag[i]) {
            o = v;                       // outlier kept exact
        } else {
            float qq = rintf(__fdiv_rn(v, scale));   // round half-to-even, IEEE div
            qq = fminf(fmaxf(qq, -QMAXF), QMAXF);
            o = qq * scale;
        }
        g_kfull[((size_t)h * SEQ + i) * DH + d] = o;
    }
}

// ---------------------------------------------------------------------------
// V quantization: one 128-thread block per (h, s) row; outliers along channels.
// ---------------------------------------------------------------------------
__global__ __launch_bounds__(128) void vquant_kernel(const float* __restrict__ vin) {
    const int row = blockIdx.x;       // h*SEQ + s
    const int tid = threadIdx.x;

    float v = vin[(size_t)row * DH + tid];
    float a = fabsf(v);

    __shared__ float sab[DH];
    sab[tid] = a;
    __syncthreads();

    // exact rank: number of entries strictly ahead of me in top_k order
    int rank = 0;
#pragma unroll 8
    for (int j = 0; j < DH; ++j) {
        float b = sab[j];
        rank += (b > a) || (b == a && j < tid);
    }
    const bool outl = (rank < NOUT);

    float da = outl ? 0.0f : a;
#pragma unroll
    for (int o = 16; o > 0; o >>= 1)
        da = fmaxf(da, __shfl_xor_sync(0xffffffffu, da, o));
    __shared__ float wmax[4];
    if ((tid & 31) == 0) wmax[tid >> 5] = da;
    __syncthreads();
    float mx = fmaxf(fmaxf(wmax[0], wmax[1]), fmaxf(wmax[2], wmax[3]));
    float scale = fmaxf(mx, 1e-6f) / QMAXF;

    float o;
    if (outl) {
        o = v;
    } else {
        float qq = rintf(__fdiv_rn(v, scale));
        qq = fminf(fmaxf(qq, -QMAXF), QMAXF);
        o = qq * scale;
    }
    g_vfull[(size_t)row * DH + tid] = o;
}

// ---------------------------------------------------------------------------
// Causal flash attention (fp32). One block per (head, q-tile of 64 rows).
// ---------------------------------------------------------------------------
extern __shared__ float smem[];

__global__ __launch_bounds__(256) void attn_kernel(const float* __restrict__ qin,
                                                   float* __restrict__ out) {
    float* sQ = smem;                    // 64 x QSTR
    float* sK = sQ + BM * QSTR;          // 64 x QSTR
    float* sV = sK + BN * QSTR;          // 64 x QSTR
    float* sP = sV + BN * QSTR;          // 64 x PSTR

    const int tid = threadIdx.x;
    const int bx  = blockIdx.x;
    const int h   = bx >> 5;
    const int qt  = 31 - (bx & 31);      // heavy (causal-long) tiles first
    const int qglob = qt * BM;

    // ---- load Q tile (coalesced float4) ----
    const float* qbase = qin + ((size_t)h * SEQ + qglob) * DH;
    for (int i = tid; i < BM * 32; i += 256) {
        int r = i >> 5, c = i & 31;
        *(float4*)&sQ[r * QSTR + c * 4] = ((const float4*)qbase)[r * 32 + c];
    }

    const int ti = tid >> 4, tj = tid & 15;       // QK mapping: 16x16 grid, 4x4 micro
    const int prow = tid >> 2, pg = tid & 3;      // softmax/PV mapping: 64 rows x 4 lanes

    float acc[32];
#pragma unroll
    for (int j = 0; j < 32; ++j) acc[j] = 0.0f;
    float mrow = -INFINITY, lrow = 0.0f;
    const float sm_scale = 0.08838834764831845f;  // 1/sqrt(128)

    const float* kbase = g_kfull + (size_t)h * SEQ * DH;
    const float* vbase = g_vfull + (size_t)h * SEQ * DH;

    for (int kt = 0; kt <= qt; ++kt) {
        __syncthreads();   // protect sK/sV vs previous PV stage
        const float* kb = kbase + (size_t)kt * BN * DH;
        const float* vb = vbase + (size_t)kt * BN * DH;
        for (int i = tid; i < BN * 32; i += 256) {
            int r = i >> 5, c = i & 31;
            *(float4*)&sK[r * QSTR + c * 4] = ((const float4*)kb)[r * 32 + c];
            *(float4*)&sV[r * QSTR + c * 4] = ((const float4*)vb)[r * 32 + c];
        }
        __syncthreads();

        // ---- S = Q K^T (4x4 register tile per thread; conflict-free LDS) ----
        float sc[4][4];
#pragma unroll
        for (int i = 0; i < 4; ++i)
#pragma unroll
            for (int j = 0; j < 4; ++j) sc[i][j] = 0.0f;

#pragma unroll 4
        for (int d4 = 0; d4 < 32; ++d4) {
            float4 qv[4], kv[4];
#pragma unroll
            for (int i = 0; i < 4; ++i) qv[i] = *(const float4*)&sQ[(ti + 16 * i) * QSTR + d4 * 4];
#pragma unroll
            for (int j = 0; j < 4; ++j) kv[j] = *(const float4*)&sK[(tj + 16 * j) * QSTR + d4 * 4];
#pragma unroll
            for (int i = 0; i < 4; ++i)
#pragma unroll
                for (int j = 0; j < 4; ++j) {
                    sc[i][j] += qv[i].x * kv[j].x + qv[i].y * kv[j].y
                              + qv[i].z * kv[j].z + qv[i].w * kv[j].w;
                }
        }

        const bool diag = (kt == qt);
#pragma unroll
        for (int i = 0; i < 4; ++i) {
            int r = ti + 16 * i;
#pragma unroll
            for (int j = 0; j < 4; ++j) {
                int c = tj + 16 * j;
                float s = sc[i][j] * sm_scale;
                if (diag && (kt * BN + c > qglob + r)) s = -1e30f;
                sP[r * PSTR + c] = s;
            }
        }
        __syncthreads();

        // ---- online softmax (4 lanes per row) ----
        float tm = -INFINITY;
        float svv[16];
#pragma unroll
        for (int jj = 0; jj < 16; ++jj) {
            float s = sP[prow * PSTR + pg + 4 * jj];
            svv[jj] = s;
            tm = fmaxf(tm, s);
        }
        tm = fmaxf(tm, __shfl_xor_sync(0xffffffffu, tm, 1));
        tm = fmaxf(tm, __shfl_xor_sync(0xffffffffu, tm, 2));
        float newm = fmaxf(mrow, tm);
        float corr = expf(mrow - newm);
        float rsum = 0.0f;
#pragma unroll
        for (int jj = 0; jj < 16; ++jj) {
            float p = expf(svv[jj] - newm);
            sP[prow * PSTR + pg + 4 * jj] = p;
            rsum += p;
        }
        rsum += __shfl_xor_sync(0xffffffffu, rsum, 1);
        rsum += __shfl_xor_sync(0xffffffffu, rsum, 2);
        lrow = lrow * corr + rsum;
        mrow = newm;
#pragma unroll
        for (int j = 0; j < 32; ++j) acc[j] *= corr;
        __syncthreads();

        // ---- O += P V (channels interleaved: ch = pg*4 + 16*mm + 0..3) ----
        for (int k = 0; k < BN; ++k) {
            float p = sP[prow * PSTR + k];
#pragma unroll
            for (int mm = 0; mm < 8; ++mm) {
                float4 v = *(const float4*)&sV[k * QSTR + pg * 4 + 16 * mm];
                acc[mm * 4 + 0] += p * v.x;
                acc[mm * 4 + 1] += p * v.y;
                acc[mm * 4 + 2] += p * v.z;
                acc[mm * 4 + 3] += p * v.w;
            }
        }
    }

    // ---- write output ----
    const float invl = 1.0f / lrow;
    float* ob = out + ((size_t)h * SEQ + qglob + prow) * DH;
#pragma unroll
    for (int mm = 0; mm < 8; ++mm) {
        float4 v;
        v.x = acc[mm * 4 + 0] * invl;
        v.y = acc[mm * 4 + 1] * invl;
        v.z = acc[mm * 4 + 2] * invl;
        v.w = acc[mm * 4 + 3] * invl;
        *(float4*)&ob[pg * 4 + 16 * mm] = v;
    }
}

// ---------------------------------------------------------------------------
extern "C" void kernel_launch(void* const* d_in, const int* in_sizes, int n_in,
                              void* d_out, int out_size) {
    const float* q = (const float*)d_in[0];
    const float* k = (const float*)d_in[1];
    const float* v = (const float*)d_in[2];
    float* out = (float*)d_out;

    kquant_kernel<<<H * DH, 256>>>(k);
    vquant_kernel<<<H * SEQ, 128>>>(v);

    const int smem_bytes = (3 * BM * QSTR + BM * PSTR) * (int)sizeof(float); // 118784
    cudaFuncSetAttribute(attn_kernel, cudaFuncAttributeMaxDynamicSharedMemorySize, smem_bytes);
    attn_kernel<<<H * (SEQ / BM), 256, smem_bytes>>>(q, out);
}

// round 4
// speedup vs baseline: 2.7759x; 2.7759x over previous
#include <cuda_runtime.h>
#include <cuda_bf16.h>
#include <math.h>
#include <stdint.h>

#define H   32
#define SEQ 2048
#define DH  128
#define NOUT 16
#define QMAXF 7.0f

// ---------------------------------------------------------------------------
// Scratch globals
// ---------------------------------------------------------------------------
__device__ float g_kfull[(size_t)H * SEQ * DH];
__device__ float g_vfull[(size_t)H * SEQ * DH];
__device__ __align__(16) __nv_bfloat16 g_khi[(size_t)H * SEQ * DH];
__device__ __align__(16) __nv_bfloat16 g_klo[(size_t)H * SEQ * DH];
__device__ __align__(16) __nv_bfloat16 g_vthi[(size_t)H * DH * SEQ];  // [h][d][s]
__device__ __align__(16) __nv_bfloat16 g_vtlo[(size_t)H * DH * SEQ];

static __device__ __forceinline__ uint32_t pack_bf16(__nv_bfloat16 a, __nv_bfloat16 b) {
    return (uint32_t)__bfloat16_as_ushort(a) | ((uint32_t)__bfloat16_as_ushort(b) << 16);
}
__device__ __forceinline__ uint32_t smem_u32(const void* p) {
    uint32_t a;
    asm("{ .reg .u64 t; cvta.to.shared.u64 t, %1; cvt.u32.u64 %0, t; }" : "=r"(a) : "l"(p));
    return a;
}
__device__ __forceinline__ void ldmx2(uint32_t& r0, uint32_t& r1, uint32_t addr) {
    asm volatile("ldmatrix.sync.aligned.m8n8.x2.shared.b16 {%0,%1}, [%2];"
                 : "=r"(r0), "=r"(r1) : "r"(addr));
}
__device__ __forceinline__ void mma_bf16(float* c, const uint32_t* a, uint32_t b0, uint32_t b1) {
    asm volatile("mma.sync.aligned.m16n8k16.row.col.f32.bf16.bf16.f32 "
                 "{%0,%1,%2,%3}, {%4,%5,%6,%7}, {%8,%9}, {%0,%1,%2,%3};"
                 : "+f"(c[0]), "+f"(c[1]), "+f"(c[2]), "+f"(c[3])
                 : "r"(a[0]), "r"(a[1]), "r"(a[2]), "r"(a[3]), "r"(b0), "r"(b1));
}

// ---------------------------------------------------------------------------
// K quantization: one block per (h, d) slice; outliers along the token axis.
// ---------------------------------------------------------------------------
__global__ __launch_bounds__(256) void kquant_kernel(const float* __restrict__ kin) {
    const int slice = blockIdx.x;
    const int h = slice >> 7;
    const int d = slice & 127;
    const int tid = threadIdx.x;

    __shared__ float sval[SEQ];
    __shared__ float sabs[SEQ];
    __shared__ unsigned char sflag[SEQ];
    __shared__ float rv[256];
    __shared__ int   ri[256];

    const float* base = kin + (size_t)h * SEQ * DH + d;
    for (int i = tid; i < SEQ; i += 256) {
        float v = base[(size_t)i * DH];
        sval[i] = v; sabs[i] = fabsf(v); sflag[i] = 0;
    }
    __syncthreads();

    for (int it = 0; it < NOUT; ++it) {
        float bm = -1.0f; int bi = 0x7fffffff;
        for (int i = tid; i < SEQ; i += 256) {
            float a = sabs[i];
            if (a > bm || (a == bm && i < bi)) { bm = a; bi = i; }
        }
        rv[tid] = bm; ri[tid] = bi;
        __syncthreads();
        for (int sft = 128; sft > 0; sft >>= 1) {
            if (tid < sft) {
                float a = rv[tid + sft]; int b = ri[tid + sft];
                if (a > rv[tid] || (a == rv[tid] && b < ri[tid])) { rv[tid] = a; ri[tid] = b; }
            }
            __syncthreads();
        }
        if (tid == 0) { int w = ri[0]; sflag[w] = 1; sabs[w] = -1.0f; }
        __syncthreads();
    }

    {
        float bm = 0.0f;
        for (int i = tid; i < SEQ; i += 256) bm = fmaxf(bm, sabs[i]);
        rv[tid] = bm;
        __syncthreads();
        for (int sft = 128; sft > 0; sft >>= 1) {
            if (tid < sft) rv[tid] = fmaxf(rv[tid], rv[tid + sft]);
            __syncthreads();
        }
    }
    const float scale = fmaxf(rv[0], 1e-6f) / QMAXF;

    for (int i = tid; i < SEQ; i += 256) {
        float v = sval[i];
        float o;
        if (sflag[i]) o = v;
        else {
            float qq = rintf(__fdiv_rn(v, scale));
            qq = fminf(fmaxf(qq, -QMAXF), QMAXF);
            o = qq * scale;
        }
        g_kfull[((size_t)h * SEQ + i) * DH + d] = o;
    }
}

// ---------------------------------------------------------------------------
// V quantization: one 128-thread block per (h, s) row.
// ---------------------------------------------------------------------------
__global__ __launch_bounds__(128) void vquant_kernel(const float* __restrict__ vin) {
    const int row = blockIdx.x;
    const int tid = threadIdx.x;

    float v = vin[(size_t)row * DH + tid];
    float a = fabsf(v);

    __shared__ float sab[DH];
    sab[tid] = a;
    __syncthreads();

    int rank = 0;
#pragma unroll 8
    for (int j = 0; j < DH; ++j) {
        float b = sab[j];
        rank += (b > a) || (b == a && j < tid);
    }
    const bool outl = (rank < NOUT);

    float da = outl ? 0.0f : a;
#pragma unroll
    for (int o = 16; o > 0; o >>= 1) da = fmaxf(da, __shfl_xor_sync(0xffffffffu, da, o));
    __shared__ float wmax[4];
    if ((tid & 31) == 0) wmax[tid >> 5] = da;
    __syncthreads();
    float mx = fmaxf(fmaxf(wmax[0], wmax[1]), fmaxf(wmax[2], wmax[3]));
    float scale = fmaxf(mx, 1e-6f) / QMAXF;

    float o;
    if (outl) o = v;
    else {
        float qq = rintf(__fdiv_rn(v, scale));
        qq = fminf(fmaxf(qq, -QMAXF), QMAXF);
        o = qq * scale;
    }
    g_vfull[(size_t)row * DH + tid] = o;
}

// ---------------------------------------------------------------------------
// K split: fp32 [h][s][d] -> bf16 hi/lo planes (coalesced)
// ---------------------------------------------------------------------------
__global__ __launch_bounds__(256) void ksplit_kernel() {
    size_t i = (size_t)blockIdx.x * 256 + threadIdx.x;
    float4 v = ((const float4*)g_kfull)[i];
    __nv_bfloat16 hx = __float2bfloat16_rn(v.x), hy = __float2bfloat16_rn(v.y);
    __nv_bfloat16 hz = __float2bfloat16_rn(v.z), hw = __float2bfloat16_rn(v.w);
    __nv_bfloat16 lx = __float2bfloat16_rn(v.x - __bfloat162float(hx));
    __nv_bfloat16 ly = __float2bfloat16_rn(v.y - __bfloat162float(hy));
    __nv_bfloat16 lz = __float2bfloat16_rn(v.z - __bfloat162float(hz));
    __nv_bfloat16 lw = __float2bfloat16_rn(v.w - __bfloat162float(hw));
    uint2 hv, lv;
    hv.x = pack_bf16(hx, hy); hv.y = pack_bf16(hz, hw);
    lv.x = pack_bf16(lx, ly); lv.y = pack_bf16(lz, lw);
    ((uint2*)g_khi)[i] = hv;
    ((uint2*)g_klo)[i] = lv;
}

// ---------------------------------------------------------------------------
// V transpose + split: fp32 [h][s][d] -> bf16 hi/lo [h][d][s]
// ---------------------------------------------------------------------------
__global__ void vtrans_kernel() {
    __shared__ float t[32][33];
    const int s0 = blockIdx.x * 32, d0 = blockIdx.y * 32, h = blockIdx.z;
    const int tx = threadIdx.x, ty = threadIdx.y;
    t[ty][tx] = g_vfull[((size_t)h * SEQ + s0 + ty) * DH + d0 + tx];
    __syncthreads();
    float v = t[tx][ty];
    __nv_bfloat16 hi = __float2bfloat16_rn(v);
    __nv_bfloat16 lo = __float2bfloat16_rn(v - __bfloat162float(hi));
    size_t o = ((size_t)h * DH + d0 + ty) * SEQ + s0 + tx;
    g_vthi[o] = hi;
    g_vtlo[o] = lo;
}

// ---------------------------------------------------------------------------
// FA2 split-bf16 mma.sync flash attention.
// Block = 128 threads (4 warps), BM = 64 q-rows (16/warp), BN = 64, D = 128.
// smem layout (bytes):
//   sKhi  [64 rows][272 B]   @ 0        (17408)
//   sKlo                     @ 17408    (17408)
//   sVhi  [128 rows][144 B]  @ 34816    (18432)
//   sVlo                     @ 53248    (18432)
//   (Q fp32 staging [64][132] floats overlays the V region before the loop)
// ---------------------------------------------------------------------------
#define SK_HI 0
#define SK_LO 17408
#define SV_HI 34816
#define SV_LO 53248
#define ATTN_SMEM 71680
#define KSTRB 272
#define VSTRB 144

extern __shared__ char sm_dyn[];

__global__ __launch_bounds__(128, 1)
void attn_mma_kernel(const float* __restrict__ qin, float* __restrict__ out) {
    const uint32_t sb = smem_u32(sm_dyn);
    const int tid  = threadIdx.x;
    const int w    = tid >> 5;
    const int lane = tid & 31;
    const int bx = blockIdx.x;
    const int h  = bx & 31;
    const int qt = 31 - (bx >> 5);          // heavy tiles first
    const int qglob = qt * 64;

    const int quad = lane >> 2;             // 0..7  (row within 8)
    const int qtr  = lane & 3;              // 0..3  (col pair)
    const int r0 = w * 16 + quad;           // warp-local q row
    const int rowg0 = qglob + r0;
    const int rowg1 = rowg0 + 8;

    // ---- stage Q (scaled) as fp32 into smem, build A-fragments ----
    float* sQf = (float*)(sm_dyn + SV_HI);  // [64][132]
    {
        const float sms = 0.08838834764831845f;
        const float4* qbase = (const float4*)(qin + ((size_t)h * SEQ + qglob) * DH);
        for (int i = tid; i < 64 * 32; i += 128) {
            int r = i >> 5, c = i & 31;
            float4 v = qbase[r * 32 + c];
            v.x *= sms; v.y *= sms; v.z *= sms; v.w *= sms;
            *(float4*)&sQf[r * 132 + c * 4] = v;
        }
    }
    __syncthreads();

    uint32_t qhi[8][4], qlo[8][4];
    {
        const float* s0 = &sQf[r0 * 132];
        const float* s1 = &sQf[(r0 + 8) * 132];
#pragma unroll
        for (int kf = 0; kf < 8; ++kf) {
            int k0 = kf * 16 + 2 * qtr;
            float e[4][2] = {{s0[k0], s0[k0 + 1]}, {s1[k0], s1[k0 + 1]},
                             {s0[k0 + 8], s0[k0 + 9]}, {s1[k0 + 8], s1[k0 + 9]}};
#pragma unroll
            for (int j = 0; j < 4; ++j) {
                __nv_bfloat16 h0 = __float2bfloat16_rn(e[j][0]);
                __nv_bfloat16 h1 = __float2bfloat16_rn(e[j][1]);
                __nv_bfloat16 l0 = __float2bfloat16_rn(e[j][0] - __bfloat162float(h0));
                __nv_bfloat16 l1 = __float2bfloat16_rn(e[j][1] - __bfloat162float(h1));
                qhi[kf][j] = pack_bf16(h0, h1);
                qlo[kf][j] = pack_bf16(l0, l1);
            }
        }
    }
    __syncthreads();   // Q staging region will be overwritten by V tiles

    // ldmatrix base addresses (lanes 0-15 meaningful for .x2)
    const int l8 = lane & 7;
    const int lh = (lane >> 3) & 1;
    const uint32_t kmxH = sb + SK_HI + l8 * KSTRB + lh * 16;
    const uint32_t kmxL = sb + SK_LO + l8 * KSTRB + lh * 16;
    const uint32_t vmxH = sb + SV_HI + l8 * VSTRB + lh * 16;
    const uint32_t vmxL = sb + SV_LO + l8 * VSTRB + lh * 16;

    const __nv_bfloat16* khi_h = g_khi + (size_t)h * SEQ * DH;
    const __nv_bfloat16* klo_h = g_klo + (size_t)h * SEQ * DH;
    const __nv_bfloat16* vhi_h = g_vthi + (size_t)h * DH * SEQ;
    const __nv_bfloat16* vlo_h = g_vtlo + (size_t)h * DH * SEQ;

    float O[16][4];
#pragma unroll
    for (int i = 0; i < 16; ++i)
#pragma unroll
        for (int j = 0; j < 4; ++j) O[i][j] = 0.0f;
    float m0 = -INFINITY, m1 = -INFINITY, l0 = 0.0f, l1 = 0.0f;

    for (int kt = 0; kt <= qt; ++kt) {
        // ---- load K hi/lo [64][128] and V^T hi/lo [128][64] tiles ----
        {
            const uint4* kb0 = (const uint4*)(khi_h + (size_t)kt * 64 * DH);
            const uint4* kb1 = (const uint4*)(klo_h + (size_t)kt * 64 * DH);
#pragma unroll
            for (int i = tid; i < 1024; i += 128) {
                int r = i >> 4, c = i & 15;
                uint32_t sa = r * KSTRB + c * 16;
                *(uint4*)(sm_dyn + SK_HI + sa) = kb0[r * 16 + c];
                *(uint4*)(sm_dyn + SK_LO + sa) = kb1[r * 16 + c];
            }
            const __nv_bfloat16* vb0 = vhi_h + (size_t)kt * 64;
            const __nv_bfloat16* vb1 = vlo_h + (size_t)kt * 64;
#pragma unroll
            for (int i = tid; i < 1024; i += 128) {
                int r = i >> 3, c = i & 7;
                uint32_t sa = r * VSTRB + c * 16;
                *(uint4*)(sm_dyn + SV_HI + sa) = ((const uint4*)(vb0 + (size_t)r * SEQ))[c];
                *(uint4*)(sm_dyn + SV_LO + sa) = ((const uint4*)(vb1 + (size_t)r * SEQ))[c];
            }
        }
        __syncthreads();

        // ---- S = Q K^T : 8 n-frags, 8 k-frags, 3-term split ----
        float Sc[8][4];
#pragma unroll
        for (int nf = 0; nf < 8; ++nf) {
            Sc[nf][0] = Sc[nf][1] = Sc[nf][2] = Sc[nf][3] = 0.0f;
            uint32_t nof = nf * 8 * KSTRB;
#pragma unroll
            for (int kf = 0; kf < 8; ++kf) {
                uint32_t b0h, b1h, b0l, b1l;
                ldmx2(b0h, b1h, kmxH + nof + kf * 32);
                ldmx2(b0l, b1l, kmxL + nof + kf * 32);
                mma_bf16(Sc[nf], qhi[kf], b0h, b1h);
                mma_bf16(Sc[nf], qhi[kf], b0l, b1l);
                mma_bf16(Sc[nf], qlo[kf], b0h, b1h);
            }
        }

        // ---- causal mask (diagonal tile only) ----
        if (kt == qt) {
            int cb = kt * 64 + 2 * qtr;
#pragma unroll
            for (int nf = 0; nf < 8; ++nf) {
                int c0 = cb + nf * 8, c1 = c0 + 1;
                if (c0 > rowg0) Sc[nf][0] = -1e30f;
                if (c1 > rowg0) Sc[nf][1] = -1e30f;
                if (c0 > rowg1) Sc[nf][2] = -1e30f;
                if (c1 > rowg1) Sc[nf][3] = -1e30f;
            }
        }

        // ---- online softmax ----
        float t0 = -INFINITY, t1 = -INFINITY;
#pragma unroll
        for (int nf = 0; nf < 8; ++nf) {
            t0 = fmaxf(t0, fmaxf(Sc[nf][0], Sc[nf][1]));
            t1 = fmaxf(t1, fmaxf(Sc[nf][2], Sc[nf][3]));
        }
        t0 = fmaxf(t0, __shfl_xor_sync(0xffffffffu, t0, 1));
        t0 = fmaxf(t0, __shfl_xor_sync(0xffffffffu, t0, 2));
        t1 = fmaxf(t1, __shfl_xor_sync(0xffffffffu, t1, 1));
        t1 = fmaxf(t1, __shfl_xor_sync(0xffffffffu, t1, 2));
        float n0 = fmaxf(m0, t0), n1 = fmaxf(m1, t1);
        float c0 = __expf(m0 - n0), c1 = __expf(m1 - n1);
        m0 = n0; m1 = n1;

        float rs0 = 0.0f, rs1 = 0.0f;
#pragma unroll
        for (int nf = 0; nf < 8; ++nf) {
            Sc[nf][0] = __expf(Sc[nf][0] - n0);
            Sc[nf][1] = __expf(Sc[nf][1] - n0);
            Sc[nf][2] = __expf(Sc[nf][2] - n1);
            Sc[nf][3] = __expf(Sc[nf][3] - n1);
            rs0 += Sc[nf][0] + Sc[nf][1];
            rs1 += Sc[nf][2] + Sc[nf][3];
        }
        rs0 += __shfl_xor_sync(0xffffffffu, rs0, 1);
        rs0 += __shfl_xor_sync(0xffffffffu, rs0, 2);
        rs1 += __shfl_xor_sync(0xffffffffu, rs1, 1);
        rs1 += __shfl_xor_sync(0xffffffffu, rs1, 2);
        l0 = l0 * c0 + rs0;
        l1 = l1 * c1 + rs1;
#pragma unroll
        for (int i = 0; i < 16; ++i) {
            O[i][0] *= c0; O[i][1] *= c0;
            O[i][2] *= c1; O[i][3] *= c1;
        }

        // ---- P fragments (hi/lo split, built in registers) ----
        uint32_t phi[4][4], plo[4][4];
#pragma unroll
        for (int kv = 0; kv < 4; ++kv) {
            const float* e0 = Sc[2 * kv];
            const float* e1 = Sc[2 * kv + 1];
            float src[4][2] = {{e0[0], e0[1]}, {e0[2], e0[3]}, {e1[0], e1[1]}, {e1[2], e1[3]}};
#pragma unroll
            for (int j = 0; j < 4; ++j) {
                __nv_bfloat16 h0 = __float2bfloat16_rn(src[j][0]);
                __nv_bfloat16 h1 = __float2bfloat16_rn(src[j][1]);
                __nv_bfloat16 l0b = __float2bfloat16_rn(src[j][0] - __bfloat162float(h0));
                __nv_bfloat16 l1b = __float2bfloat16_rn(src[j][1] - __bfloat162float(h1));
                phi[kv][j] = pack_bf16(h0, h1);
                plo[kv][j] = pack_bf16(l0b, l1b);
            }
        }

        // ---- O += P V (V^T in smem, 16 n-frags over d, 4 k-frags over s) ----
#pragma unroll
        for (int nf = 0; nf < 16; ++nf) {
            uint32_t nof = nf * 8 * VSTRB;
#pragma unroll
            for (int kv = 0; kv < 4; ++kv) {
                uint32_t b0h, b1h, b0l, b1l;
                ldmx2(b0h, b1h, vmxH + nof + kv * 32);
                ldmx2(b0l, b1l, vmxL + nof + kv * 32);
                mma_bf16(O[nf], phi[kv], b0h, b1h);
                mma_bf16(O[nf], phi[kv], b0l, b1l);
                mma_bf16(O[nf], plo[kv], b0h, b1h);
            }
        }
        __syncthreads();
    }

    // ---- epilogue ----
    const float i0 = 1.0f / l0, i1 = 1.0f / l1;
    float* ob0 = out + ((size_t)h * SEQ + rowg0) * DH + 2 * qtr;
    float* ob1 = out + ((size_t)h * SEQ + rowg1) * DH + 2 * qtr;
#pragma unroll
    for (int nf = 0; nf < 16; ++nf) {
        float2 a; a.x = O[nf][0] * i0; a.y = O[nf][1] * i0;
        float2 b; b.x = O[nf][2] * i1; b.y = O[nf][3] * i1;
        *(float2*)(ob0 + nf * 8) = a;
        *(float2*)(ob1 + nf * 8) = b;
    }
}

// ---------------------------------------------------------------------------
extern "C" void kernel_launch(void* const* d_in, const int* in_sizes, int n_in,
                              void* d_out, int out_size) {
    const float* q = (const float*)d_in[0];
    const float* k = (const float*)d_in[1];
    const float* v = (const float*)d_in[2];
    float* out = (float*)d_out;

    kquant_kernel<<<H * DH, 256>>>(k);
    vquant_kernel<<<H * SEQ, 128>>>(v);
    ksplit_kernel<<<(H * SEQ * DH / 4) / 256, 256>>>();
    vtrans_kernel<<<dim3(SEQ / 32, DH / 32, H), dim3(32, 32)>>>();

    cudaFuncSetAttribute(attn_mma_kernel, cudaFuncAttributeMaxDynamicSharedMemorySize, ATTN_SMEM);
    attn_mma_kernel<<<H * 32, 128, ATTN_SMEM>>>(q, out);
}